// round 7
// baseline (speedup 1.0000x reference)
#include <cuda_runtime.h>
#include <cstdint>

// VectorQuantizer: x [32,64,64,64] fp32, emb [512,64] fp32.
// Per pixel: argmin_k fl(fl(xsq+esq[k]) - 2*dot), dot = sequential ascending-d FMA chain.
// Then out[b,:,h,w] = emb[argmin].
//
// FFMA2 GEMM, zero inner-loop MOVs:
//   x staged as packed pixel pairs   xs[d][pp]   = {x[2pp], x[2pp+1]}
//   e staged pre-DUPLICATED          es[d][k]    = {e[k], e[k]}
//   thread tile: 4 pixel-pairs (8 px) x 8 codes = 32 FFMA2 per d.
//   Inner loop per d: 2 LDS.128 (x) + 4 LDS.128 (e) + 32 FFMA2.
// Block: 256 thr, tile 128 px x 128 codes, 4 k-tiles. 2 blocks/SM (dyn smem ~97.5KB).

#define KCODES 512
#define DDIM   64
#define PT     128
#define KT     128
#define NKT    (KCODES / KT)   // 4
#define NTHR   256

// dynamic smem layout (bytes)
#define XS_OFF    0                        // float2 xs[64][64]   = 32768
#define ES_OFF    32768                    // float2 es[64][128]  = 65536
#define XSQ_OFF   (ES_OFF + 65536)         // float xsq[128]
#define ESQ_OFF   (XSQ_OFF + 512)          // float esq[128]
#define WIDX_OFF  (ESQ_OFF + 512)          // int   widx[128]
#define SMEM_BYTES (WIDX_OFF + 512)
// reduction arrays overlay the xs region after the mainloop:
#define RVAL_OFF  XS_OFF                   // float red_val[128][16] = 8192
#define RIDX_OFF  (XS_OFF + 8192)          // int   red_idx[128][16] = 8192

#define FMA2(acc, a, b) \
    asm("fma.rn.f32x2 %0, %1, %2, %0;" : "+l"(acc) : "l"(a), "l"(b))

__global__ __launch_bounds__(NTHR, 2)
void vq_kernel(const float* __restrict__ x,
               const float* __restrict__ emb,
               float* __restrict__ out,
               int HW, int CHW)
{
    extern __shared__ char smem_raw[];
    float2* xs  = (float2*)(smem_raw + XS_OFF);   // xs[d*64 + pp]
    float2* es  = (float2*)(smem_raw + ES_OFF);   // es[d*128 + k] = {e,e}
    float*  xsq = (float*)(smem_raw + XSQ_OFF);
    float*  esq = (float*)(smem_raw + ESQ_OFF);
    int*    widx = (int*)(smem_raw + WIDX_OFF);
    float*  red_val = (float*)(smem_raw + RVAL_OFF);
    int*    red_idx = (int*)(smem_raw + RIDX_OFF);

    const int t   = threadIdx.x;
    const int n0  = blockIdx.x * PT;
    const int b   = n0 >> 12;          // HW = 4096; tiles never cross batch
    const int hw0 = n0 & 4095;

    // ---- stage x tile as pixel pairs: xs[c][pp] = {x[b,c,hw0+2pp], x[b,c,hw0+2pp+1]} ----
    const float2* xb2 = (const float2*)(x + (size_t)b * CHW + hw0);
    #pragma unroll
    for (int it = 0; it < (DDIM * (PT / 2)) / NTHR; ++it) {   // 16 iters, coalesced
        int lin = it * NTHR + t;
        int c  = lin >> 6;
        int pp = lin & 63;
        xs[c * 64 + pp] = xb2[c * (HW / 2) + pp];
    }
    __syncthreads();

    // ---- ||x||^2 per pixel: ascending d, rounded product then add (matches jnp.sum(x*x)) ----
    if (t < PT) {
        int pp = t >> 1, comp = t & 1;
        float s = 0.0f;
        #pragma unroll 8
        for (int d = 0; d < DDIM; ++d) {
            float v = ((const float*)&xs[d * 64 + pp])[comp];
            s = __fadd_rn(s, __fmul_rn(v, v));
        }
        xsq[t] = s;
    }

    const int pxg = t & 15;   // 16 groups x (4 pixel-pairs = 8 px)
    const int kgg = t >> 4;   // 16 groups x 8 codes

    float best[8];
    int   bidx[8];
    #pragma unroll
    for (int i = 0; i < 8; ++i) { best[i] = 3.4e38f; bidx[i] = 0; }

    for (int kt = 0; kt < NKT; ++kt) {
        __syncthreads();   // xsq ready (first iter) / protect es,esq reuse
        // ---- stage e tile DUPLICATED: es[d][k] = {emb[kt*KT+k][d], same} ----
        #pragma unroll
        for (int it = 0; it < (KT * DDIM / 4) / NTHR; ++it) {  // 8 iters
            int lin = it * NTHR + t;          // 0..2047
            int d  = lin >> 5;                // 0..63
            int k4 = (lin & 31) * 4;          // 0,4,..124
            const float* eb = emb + (size_t)(kt * KT + k4) * DDIM + d;
            float v0 = eb[0 * DDIM];
            float v1 = eb[1 * DDIM];
            float v2 = eb[2 * DDIM];
            float v3 = eb[3 * DDIM];
            float4* dst = (float4*)&es[d * 128 + k4];
            dst[0] = make_float4(v0, v0, v1, v1);
            dst[1] = make_float4(v2, v2, v3, v3);
        }
        __syncthreads();
        // ---- ||e||^2 per code (ascending d, rounded product then add) ----
        if (t < KT) {
            float s = 0.0f;
            #pragma unroll 8
            for (int d = 0; d < DDIM; ++d) {
                float v = es[d * 128 + t].x;
                s = __fadd_rn(s, __fmul_rn(v, v));
            }
            esq[t] = s;
        }
        __syncthreads();

        // ---- mainloop: acc[pp][j] += xpair[pp] * edup[j], 32 FFMA2 per d ----
        uint64_t acc[4][8];
        #pragma unroll
        for (int pp = 0; pp < 4; ++pp)
            #pragma unroll
            for (int j = 0; j < 8; ++j) acc[pp][j] = 0ull;

        const uint64_t* xsu = (const uint64_t*)xs;
        const uint64_t* esu = (const uint64_t*)es;

        #pragma unroll 4
        for (int d = 0; d < DDIM; ++d) {
            const uint64_t* xp = xsu + d * 64 + pxg * 4;   // 4 pairs, 32B
            const uint64_t* ep = esu + d * 128 + kgg * 8;  // 8 dups, 64B
            uint64_t x0 = xp[0], x1 = xp[1], x2 = xp[2], x3 = xp[3];
            uint64_t e0 = ep[0], e1 = ep[1], e2 = ep[2], e3 = ep[3];
            uint64_t e4 = ep[4], e5 = ep[5], e6 = ep[6], e7 = ep[7];
            FMA2(acc[0][0], x0, e0); FMA2(acc[0][1], x0, e1);
            FMA2(acc[0][2], x0, e2); FMA2(acc[0][3], x0, e3);
            FMA2(acc[0][4], x0, e4); FMA2(acc[0][5], x0, e5);
            FMA2(acc[0][6], x0, e6); FMA2(acc[0][7], x0, e7);
            FMA2(acc[1][0], x1, e0); FMA2(acc[1][1], x1, e1);
            FMA2(acc[1][2], x1, e2); FMA2(acc[1][3], x1, e3);
            FMA2(acc[1][4], x1, e4); FMA2(acc[1][5], x1, e5);
            FMA2(acc[1][6], x1, e6); FMA2(acc[1][7], x1, e7);
            FMA2(acc[2][0], x2, e0); FMA2(acc[2][1], x2, e1);
            FMA2(acc[2][2], x2, e2); FMA2(acc[2][3], x2, e3);
            FMA2(acc[2][4], x2, e4); FMA2(acc[2][5], x2, e5);
            FMA2(acc[2][6], x2, e6); FMA2(acc[2][7], x2, e7);
            FMA2(acc[3][0], x3, e0); FMA2(acc[3][1], x3, e1);
            FMA2(acc[3][2], x3, e2); FMA2(acc[3][3], x3, e3);
            FMA2(acc[3][4], x3, e4); FMA2(acc[3][5], x3, e5);
            FMA2(acc[3][6], x3, e6); FMA2(acc[3][7], x3, e7);
        }

        // ---- fold: s = fmaf(-2, dot, fl(xsq+esq))  (==' fl(fl(xsq+esq) - fl(2*dot))'
        //      since 2*dot is exact), ascending k keeps lowest-index ties ----
        #pragma unroll
        for (int j = 0; j < 8; ++j) {
            int   kloc = kgg * 8 + j;
            int   k    = kt * KT + kloc;
            float eq   = esq[kloc];
            #pragma unroll
            for (int pp = 0; pp < 4; ++pp) {
                float lo, hi;
                asm("mov.b64 {%0, %1}, %2;" : "=f"(lo), "=f"(hi) : "l"(acc[pp][j]));
                float t0 = __fadd_rn(xsq[pxg * 8 + 2 * pp], eq);
                float t1 = __fadd_rn(xsq[pxg * 8 + 2 * pp + 1], eq);
                float s0 = __fmaf_rn(-2.0f, lo, t0);
                float s1 = __fmaf_rn(-2.0f, hi, t1);
                if (s0 < best[2 * pp])     { best[2 * pp]     = s0; bidx[2 * pp]     = k; }
                if (s1 < best[2 * pp + 1]) { best[2 * pp + 1] = s1; bidx[2 * pp + 1] = k; }
            }
        }
    }

    // ---- cross-thread argmin reduction (red arrays overlay xs; xs dead now) ----
    __syncthreads();
    #pragma unroll
    for (int i = 0; i < 8; ++i) {
        red_val[(pxg * 8 + i) * 16 + kgg] = best[i];
        red_idx[(pxg * 8 + i) * 16 + kgg] = bidx[i];
    }
    __syncthreads();
    if (t < PT) {
        float bv = red_val[t * 16 + 0];
        int   bi = red_idx[t * 16 + 0];
        #pragma unroll
        for (int g = 1; g < 16; ++g) {
            float v  = red_val[t * 16 + g];
            int   id = red_idx[t * 16 + g];
            if (v < bv || (v == bv && id < bi)) { bv = v; bi = id; }
        }
        widx[t] = bi;
    }
    __syncthreads();

    // ---- gather + write out[b, c, hw0+p] = emb[widx[p]][c] ----
    float* ob = out + (size_t)b * CHW + hw0;
    #pragma unroll
    for (int it = 0; it < (DDIM * PT) / NTHR; ++it) {
        int lin = it * NTHR + t;
        int c = lin >> 7;
        int p = lin & 127;
        ob[c * HW + p] = emb[(size_t)widx[p] * DDIM + c];
    }
}

extern "C" void kernel_launch(void* const* d_in, const int* in_sizes, int n_in,
                              void* d_out, int out_size)
{
    const float* x   = (const float*)d_in[0];   // [32, 64, 64, 64]
    const float* emb = (const float*)d_in[1];   // [512, 64]
    float* out = (float*)d_out;

    const int HW  = 64 * 64;             // 4096
    const int CHW = DDIM * HW;           // 262144
    const int N   = in_sizes[0] / DDIM;  // 131072 pixels

    cudaFuncSetAttribute(vq_kernel, cudaFuncAttributeMaxDynamicSharedMemorySize,
                         SMEM_BYTES);

    dim3 grid(N / PT);                   // 1024
    dim3 block(NTHR);
    vq_kernel<<<grid, block, SMEM_BYTES>>>(x, emb, out, HW, CHW);
}

// round 8
// speedup vs baseline: 1.1277x; 1.1277x over previous
#include <cuda_runtime.h>
#include <cstdint>

// VectorQuantizer: x [32,64,64,64] fp32, emb [512,64] fp32.
// Per pixel: argmin_k fl(fl(xsq+esq[k]) - 2*dot), dot = sequential ascending-d FMA chain.
// Then out[b,:,h,w] = emb[argmin].
//
// FFMA2 GEMM, zero inner-loop MOVs:
//   xs[d][pp] = {x[2pp], x[2pp+1]}   (natural pixel-pair packing)
//   es[d][k]  = {e[k], e[k]}         (pre-duplicated at staging, COALESCED gmem reads)
// Thread tile: 4 pixel-pairs (8 px) x 8 codes = 32 FFMA2 per d.
// Warp mapping 8 pxg x 4 kgg balances smem dedup (512B unique/warp/d).
// Block: 256 thr, tile 128 px x 128 codes, 4 k-tiles, 2 blocks/SM.

#define KCODES 512
#define DDIM   64
#define PT     128
#define KT     128
#define NKT    (KCODES / KT)   // 4
#define NTHR   256

// dynamic smem layout (bytes)
#define XS_OFF     0                         // float2 xs[64][64]   = 32768
#define ES_OFF     32768                     // float2 es[64][128]  = 65536
#define XSQ_OFF    (ES_OFF + 65536)          // float xsq[128] = 512
#define ESQ_OFF    (XSQ_OFF + 512)           // float esq[128] = 512
#define WIDX_OFF   (ESQ_OFF + 512)           // int   widx[128] = 512
#define SMEM_BYTES (WIDX_OFF + 512)          // 99840 -> 2 blocks/SM (199.7KB <= 228KB)
// reduction arrays overlay xs after the mainloop:
#define RVAL_OFF   XS_OFF                    // float red_val[128][16] = 8192
#define RIDX_OFF   (XS_OFF + 8192)           // int   red_idx[128][16] = 8192

#define FMA2(acc, a, b) \
    asm("fma.rn.f32x2 %0, %1, %2, %0;" : "+l"(acc) : "l"(a), "l"(b))

__global__ __launch_bounds__(NTHR, 2)
void vq_kernel(const float* __restrict__ x,
               const float* __restrict__ emb,
               float* __restrict__ out,
               int HW, int CHW)
{
    extern __shared__ char smem_raw[];
    float2* xs   = (float2*)(smem_raw + XS_OFF);   // xs[d*64 + pp]
    float2* es   = (float2*)(smem_raw + ES_OFF);   // es[d*128 + k] = {e,e}
    float*  xsq  = (float*)(smem_raw + XSQ_OFF);
    float*  esq  = (float*)(smem_raw + ESQ_OFF);
    int*    widx = (int*)(smem_raw + WIDX_OFF);
    float*  red_val = (float*)(smem_raw + RVAL_OFF);
    int*    red_idx = (int*)(smem_raw + RIDX_OFF);

    const int t   = threadIdx.x;
    const int n0  = blockIdx.x * PT;
    const int b   = n0 >> 12;          // HW = 4096; tiles never cross batch
    const int hw0 = n0 & 4095;

    // ---- stage x tile as pixel pairs (coalesced float2) ----
    const float2* xb2 = (const float2*)(x + (size_t)b * CHW + hw0);
    #pragma unroll
    for (int it = 0; it < (DDIM * (PT / 2)) / NTHR; ++it) {   // 16 iters
        int lin = it * NTHR + t;
        int c  = lin >> 6;
        int pp = lin & 63;
        xs[c * 64 + pp] = xb2[c * (HW / 2) + pp];
    }
    __syncthreads();

    // ---- ||x||^2 per pixel: ascending d, rounded product then add ----
    if (t < PT) {
        int pp = t >> 1, comp = t & 1;
        float s = 0.0f;
        #pragma unroll 8
        for (int d = 0; d < DDIM; ++d) {
            float v = ((const float*)&xs[d * 64 + pp])[comp];
            s = __fadd_rn(s, __fmul_rn(v, v));
        }
        xsq[t] = s;
    }

    // warp-balanced mapping: per warp 8 pxg x 4 kgg
    const int pxg = (t & 7) | ((t >> 4) & 8);   // 0..15, 4 pixel-pairs each (8 px)
    const int kgg = (t >> 3) & 15;              // 0..15, 8 codes each

    float best[8];
    int   bidx[8];
    #pragma unroll
    for (int i = 0; i < 8; ++i) { best[i] = 3.4e38f; bidx[i] = 0; }

    for (int kt = 0; kt < NKT; ++kt) {
        __syncthreads();   // xsq ready (1st iter) / protect es,esq reuse
        // ---- stage e tile DUPLICATED, gmem reads COALESCED float4 ----
        #pragma unroll
        for (int it = 0; it < (KT * DDIM / 4) / NTHR; ++it) {  // 8 iters
            int lin = it * NTHR + t;          // 0..2047
            int k   = lin >> 4;               // 0..127
            int d4  = (lin & 15) * 4;         // consecutive lanes -> consecutive d4
            float4 ev = *(const float4*)(emb + (size_t)(kt * KT + k) * DDIM + d4);
            es[(d4 + 0) * 128 + k] = make_float2(ev.x, ev.x);
            es[(d4 + 1) * 128 + k] = make_float2(ev.y, ev.y);
            es[(d4 + 2) * 128 + k] = make_float2(ev.z, ev.z);
            es[(d4 + 3) * 128 + k] = make_float2(ev.w, ev.w);
        }
        __syncthreads();
        // ---- ||e||^2 per code (ascending d) ----
        if (t < KT) {
            float s = 0.0f;
            #pragma unroll 8
            for (int d = 0; d < DDIM; ++d) {
                float v = es[d * 128 + t].x;
                s = __fadd_rn(s, __fmul_rn(v, v));
            }
            esq[t] = s;
        }
        __syncthreads();

        // ---- mainloop: 2 LDS.128 (x) + 4 LDS.128 (e) + 32 FFMA2 per d ----
        uint64_t acc[4][8];
        #pragma unroll
        for (int pp = 0; pp < 4; ++pp)
            #pragma unroll
            for (int j = 0; j < 8; ++j) acc[pp][j] = 0ull;

        const uint64_t* xsu = (const uint64_t*)xs + pxg * 4;
        const uint64_t* esu = (const uint64_t*)es + kgg * 8;

        #pragma unroll 8
        for (int d = 0; d < DDIM; ++d) {
            const uint64_t* xp = xsu + d * 64;
            const uint64_t* ep = esu + d * 128;
            uint64_t x0 = xp[0], x1 = xp[1], x2 = xp[2], x3 = xp[3];
            uint64_t e0 = ep[0], e1 = ep[1], e2 = ep[2], e3 = ep[3];
            uint64_t e4 = ep[4], e5 = ep[5], e6 = ep[6], e7 = ep[7];
            FMA2(acc[0][0], x0, e0); FMA2(acc[0][1], x0, e1);
            FMA2(acc[0][2], x0, e2); FMA2(acc[0][3], x0, e3);
            FMA2(acc[0][4], x0, e4); FMA2(acc[0][5], x0, e5);
            FMA2(acc[0][6], x0, e6); FMA2(acc[0][7], x0, e7);
            FMA2(acc[1][0], x1, e0); FMA2(acc[1][1], x1, e1);
            FMA2(acc[1][2], x1, e2); FMA2(acc[1][3], x1, e3);
            FMA2(acc[1][4], x1, e4); FMA2(acc[1][5], x1, e5);
            FMA2(acc[1][6], x1, e6); FMA2(acc[1][7], x1, e7);
            FMA2(acc[2][0], x2, e0); FMA2(acc[2][1], x2, e1);
            FMA2(acc[2][2], x2, e2); FMA2(acc[2][3], x2, e3);
            FMA2(acc[2][4], x2, e4); FMA2(acc[2][5], x2, e5);
            FMA2(acc[2][6], x2, e6); FMA2(acc[2][7], x2, e7);
            FMA2(acc[3][0], x3, e0); FMA2(acc[3][1], x3, e1);
            FMA2(acc[3][2], x3, e2); FMA2(acc[3][3], x3, e3);
            FMA2(acc[3][4], x3, e4); FMA2(acc[3][5], x3, e5);
            FMA2(acc[3][6], x3, e6); FMA2(acc[3][7], x3, e7);
        }

        // ---- fold: s = fmaf(-2, dot, fl(xsq+esq)); ascending k keeps lowest idx ----
        #pragma unroll
        for (int j = 0; j < 8; ++j) {
            int   kloc = kgg * 8 + j;
            int   k    = kt * KT + kloc;
            float eq   = esq[kloc];
            #pragma unroll
            for (int pp = 0; pp < 4; ++pp) {
                float lo, hi;
                asm("mov.b64 {%0, %1}, %2;" : "=f"(lo), "=f"(hi) : "l"(acc[pp][j]));
                float t0 = __fadd_rn(xsq[pxg * 8 + 2 * pp], eq);
                float t1 = __fadd_rn(xsq[pxg * 8 + 2 * pp + 1], eq);
                float s0 = __fmaf_rn(-2.0f, lo, t0);
                float s1 = __fmaf_rn(-2.0f, hi, t1);
                if (s0 < best[2 * pp])     { best[2 * pp]     = s0; bidx[2 * pp]     = k; }
                if (s1 < best[2 * pp + 1]) { best[2 * pp + 1] = s1; bidx[2 * pp + 1] = k; }
            }
        }
    }

    // ---- cross-thread argmin reduction (red arrays overlay xs; xs dead now) ----
    __syncthreads();
    #pragma unroll
    for (int i = 0; i < 8; ++i) {
        red_val[(pxg * 8 + i) * 16 + kgg] = best[i];
        red_idx[(pxg * 8 + i) * 16 + kgg] = bidx[i];
    }
    __syncthreads();
    if (t < PT) {
        float bv = red_val[t * 16 + 0];
        int   bi = red_idx[t * 16 + 0];
        #pragma unroll
        for (int g = 1; g < 16; ++g) {
            float v  = red_val[t * 16 + g];
            int   id = red_idx[t * 16 + g];
            if (v < bv || (v == bv && id < bi)) { bv = v; bi = id; }
        }
        widx[t] = bi;
    }
    __syncthreads();

    // ---- gather + write out[b, c, hw0+p] = emb[widx[p]][c] ----
    float* ob = out + (size_t)b * CHW + hw0;
    #pragma unroll
    for (int it = 0; it < (DDIM * PT) / NTHR; ++it) {
        int lin = it * NTHR + t;
        int c = lin >> 7;
        int p = lin & 127;
        ob[c * HW + p] = emb[(size_t)widx[p] * DDIM + c];
    }
}

extern "C" void kernel_launch(void* const* d_in, const int* in_sizes, int n_in,
                              void* d_out, int out_size)
{
    const float* x   = (const float*)d_in[0];   // [32, 64, 64, 64]
    const float* emb = (const float*)d_in[1];   // [512, 64]
    float* out = (float*)d_out;

    const int HW  = 64 * 64;             // 4096
    const int CHW = DDIM * HW;           // 262144
    const int N   = in_sizes[0] / DDIM;  // 131072 pixels

    cudaFuncSetAttribute(vq_kernel, cudaFuncAttributeMaxDynamicSharedMemorySize,
                         SMEM_BYTES);

    dim3 grid(N / PT);                   // 1024
    dim3 block(NTHR);
    vq_kernel<<<grid, block, SMEM_BYTES>>>(x, emb, out, HW, CHW);
}